// round 15
// baseline (speedup 1.0000x reference)
#include <cuda_runtime.h>
#include <cuda_fp16.h>
#include <math.h>
#include <stdint.h>

#define B_    8
#define N_    1000
#define E_    4
#define D_    64
#define AD_   32
#define NE_   4000      // E_ * N_
#define ACOLS 8000      // 2 * NE_

// ---------------- scratch (device globals; no allocations allowed) ----------
__device__ __align__(16) __half g_stT [B_ * 64 * 1024];    // state transposed fp16, j padded to 1024
__device__ __align__(16) __half g_W16h[2 * E_ * 64 * 64];  // W_in/W_out fp16 hi  [io][e][f][d]
__device__ __align__(16) __half g_W16l[2 * E_ * 64 * 64];  // fp16 lo residual
__device__ __align__(16) float g_a_in [B_ * N_ * D_];
__device__ __align__(16) float g_a_out[B_ * N_ * D_];
__device__ __align__(16) float g_st1  [B_ * N_ * D_];
__device__ __align__(16) float g_st2  [B_ * N_ * D_];
// pre-transposed gate weights [k(192)][f(64)]
__device__ __align__(16) float g_WrT[192 * 64];
__device__ __align__(16) float g_WzT[192 * 64];
__device__ __align__(16) float g_WhT[192 * 64];

// ---------------- helpers ---------------------------------------------------
__device__ __forceinline__ uint32_t smem_u32(const void* p) {
    uint32_t a;
    asm("{ .reg .u64 t; cvta.to.shared.u64 t, %1; cvt.u32.u64 %0, t; }"
        : "=r"(a) : "l"(p));
    return a;
}
__device__ __forceinline__ uint32_t sw128(uint32_t off) {
    return off ^ ((off >> 3) & 0x70);
}
__device__ __forceinline__ uint32_t pack_f16x2(float v0, float v1) {
    uint32_t r;
    asm("cvt.rn.f16x2.f32 %0, %1, %2;" : "=r"(r) : "f"(v1), "f"(v0));
    return r;
}
__device__ __forceinline__ void ldsm_x4(uint32_t* d, uint32_t addr) {
    asm volatile("ldmatrix.sync.aligned.m8n8.x4.shared.b16 {%0,%1,%2,%3}, [%4];"
        : "=r"(d[0]), "=r"(d[1]), "=r"(d[2]), "=r"(d[3]) : "r"(addr));
}
__device__ __forceinline__ void ldsm_x2(uint32_t* d, uint32_t addr) {
    asm volatile("ldmatrix.sync.aligned.m8n8.x2.shared.b16 {%0,%1}, [%2];"
        : "=r"(d[0]), "=r"(d[1]) : "r"(addr));
}
__device__ __forceinline__ void mma_f16(float* c, const uint32_t* a, const uint32_t* b) {
    asm volatile("mma.sync.aligned.m16n8k16.row.col.f32.f16.f16.f32 "
        "{%0,%1,%2,%3}, {%4,%5,%6,%7}, {%8,%9}, {%0,%1,%2,%3};"
        : "+f"(c[0]), "+f"(c[1]), "+f"(c[2]), "+f"(c[3])
        : "r"(a[0]), "r"(a[1]), "r"(a[2]), "r"(a[3]), "r"(b[0]), "r"(b[1]));
}
__device__ __forceinline__ void cp_async16(uint32_t dst, const void* src, int sz) {
    asm volatile("cp.async.cg.shared.global [%0], [%1], 16, %2;"
        :: "r"(dst), "l"(src), "r"(sz) : "memory");
}
#define CP_COMMIT() asm volatile("cp.async.commit_group;" ::: "memory")
#define CP_WAIT0()  asm volatile("cp.async.wait_group 0;" ::: "memory")

// ============================================================================
// Kernel 0: one-time weight prep: gate-weight transpose + W_in/W_out fp16 hi/lo
// grid 128 x 256
// ============================================================================
__global__ __launch_bounds__(256) void k_pret(
    const float* __restrict__ W_r, const float* __restrict__ W_z,
    const float* __restrict__ W_h,
    const float* __restrict__ W_in, const float* __restrict__ W_out)
{
    int idx = blockIdx.x * 256 + threadIdx.x;   // 0..32767
    if (idx < 64 * 192) {
        int f = idx / 192, k = idx - f * 192;
        int o = k * 64 + f;
        g_WrT[o] = W_r[idx];
        g_WzT[o] = W_z[idx];
        g_WhT[o] = W_h[idx];
    }
    if (idx < 2 * E_ * 64 * 64) {
        int io  = idx >> 14;
        int rem = idx & 16383;              // e*4096 + f*64 + d
        float v = (io ? W_out : W_in)[rem];
        __half h = __float2half_rn(v);
        g_W16h[idx] = h;
        g_W16l[idx] = __float2half_rn(v - __half2float(h));
    }
}

// ============================================================================
// Kernel 1: transpose+convert state -> g_stT[b][d][j(1024, zero-padded)] fp16
// grid (16, B) x 256
// ============================================================================
__global__ __launch_bounds__(256) void k_stT(
    const float* __restrict__ prop_state, int round)
{
    const float* state = round ? g_st1 : prop_state;
    const int b = blockIdx.y, j0 = blockIdx.x * 64;
    __shared__ float tile[64][65];
    const int t = threadIdx.x;
    const float* sp = state + (size_t)b * N_ * D_;

    #pragma unroll
    for (int i = 0; i < 4; i++) {
        int idx = t + i * 256;
        int j = idx >> 4, dq = (idx & 15) << 2;
        float4 v = make_float4(0.f, 0.f, 0.f, 0.f);
        if (j0 + j < N_) v = *(const float4*)(sp + (size_t)(j0 + j) * D_ + dq);
        tile[j][dq + 0] = v.x; tile[j][dq + 1] = v.y;
        tile[j][dq + 2] = v.z; tile[j][dq + 3] = v.w;
    }
    __syncthreads();

    __half* dst = g_stT + (size_t)b * 64 * 1024;
    #pragma unroll
    for (int i = 0; i < 4; i++) {
        int idx = t + i * 256;
        int d = idx >> 4, jq = (idx & 15) << 2;
        uint2 p;
        p.x = pack_f16x2(tile[jq + 0][d], tile[jq + 1][d]);
        p.y = pack_f16x2(tile[jq + 2][d], tile[jq + 3][d]);
        *(uint2*)(dst + (size_t)d * 1024 + j0 + jq) = p;
    }
}

// ============================================================================
// Kernel 2: reordered propagation GEMM:
//   a[b,io,i,f] = sum_e ( sum_j A[b,i,io*4000+e*1000+j] * state[b,j,:] ) @ We^T
// CTA: 128-row tile, all e sequentially. B-operand (stateT) RESIDENT in smem.
// P_e accumulated in regs -> fp16 hi/lo staged -> 3-product combine with We.
// grid: (8, B, 2) ; block 256 ; smem 224KB
// ============================================================================
#define PP_ST0 0            // A stage 0 / P hi
#define PP_ST1 16384        // A stage 1 / P lo
#define PP_STT 32768        // stateT 64 x 2048B = 128KB (row-keyed swizzle)
#define PP_WH  163840       // W hi: 4e x 8KB
#define PP_WL  196608       // W lo: 4e x 8KB
#define PP_SMEM 229376

__device__ __forceinline__ void pp_prefA(
    const float* __restrict__ Ab, int i0, int e, int ch, int t, float4* ra)
{
    const int arow = t >> 4, acol = (t & 15) * 4;
    const int j = ch * 64 + acol;
    const bool jv = (j < N_);
    const float* src = Ab + e * N_ + j;
    #pragma unroll
    for (int rep = 0; rep < 8; rep++) {
        int r = i0 + arow + rep * 16;
        ra[rep] = (jv && r < N_) ? *(const float4*)(src + (size_t)r * ACOLS)
                                 : make_float4(0.f, 0.f, 0.f, 0.f);
    }
}
__device__ __forceinline__ void pp_storeA(char* stg, int t, const float4* ra)
{
    const int arow = t >> 4, acolb = (t & 15) * 8;
    #pragma unroll
    for (int rep = 0; rep < 8; rep++) {
        int r = arow + rep * 16;
        uint32_t sw = sw128((uint32_t)(r * 128 + acolb));
        uint2 hp;
        hp.x = pack_f16x2(ra[rep].x, ra[rep].y);
        hp.y = pack_f16x2(ra[rep].z, ra[rep].w);
        *(uint2*)(stg + sw) = hp;
    }
}

__global__ __launch_bounds__(256, 1) void k_prop(const float* __restrict__ A)
{
    extern __shared__ char smem[];
    const int io = blockIdx.z, b = blockIdx.y;
    const int i0 = blockIdx.x * 128;
    const int t = threadIdx.x, wid = t >> 5, lane = t & 31;
    const float* Ab = A + (size_t)b * N_ * ACOLS + (size_t)io * NE_;
    float* O = (io ? g_a_out : g_a_in) + (size_t)b * N_ * D_;
    const uint32_t sb = smem_u32(smem);

    // ---- resident loads: stateT (128KB) + W hi/lo (64KB) -------------------
    {
        const __half* st = g_stT + (size_t)b * 64 * 1024;
        #pragma unroll
        for (int r = 0; r < 32; r++) {
            int idx = t + r * 256;
            int d = idx >> 7, un = idx & 127;
            uint32_t dst = sb + PP_STT +
                (uint32_t)(d * 2048 + ((un * 16) ^ ((d & 7) << 4)));
            cp_async16(dst, st + d * 1024 + un * 8, 16);
        }
        const __half* wh = g_W16h + io * (E_ * 64 * 64);
        const __half* wl = g_W16l + io * (E_ * 64 * 64);
        #pragma unroll
        for (int r = 0; r < 8; r++) {
            int idx = t + r * 256;
            int fg = idx >> 3, un = idx & 7;
            uint32_t o2 = (uint32_t)((fg >> 6) * 8192)
                        + sw128((uint32_t)((fg & 63) * 128 + un * 16));
            cp_async16(sb + PP_WH + o2, wh + fg * 64 + un * 8, 16);
            cp_async16(sb + PP_WL + o2, wl + fg * 64 + un * 8, 16);
        }
        CP_COMMIT();
    }

    const int wm = wid & 3, wn = wid >> 2;
    const int a_r  = wm * 32 + (lane & 15);
    const int a_kb = (lane >> 4) * 16;
    const int b_rl = lane & 7;
    const int b_kb = ((lane >> 3) & 1) * 16;

    float acc2[2][4][4];
    #pragma unroll
    for (int mt = 0; mt < 2; mt++)
        #pragma unroll
        for (int nt = 0; nt < 4; nt++)
            #pragma unroll
            for (int r = 0; r < 4; r++) acc2[mt][nt][r] = 0.f;

    float4 ra[8];
    pp_prefA(Ab, i0, 0, 0, t, ra);
    CP_WAIT0();                       // resident data arrived
    pp_storeA(smem + PP_ST0, t, ra);
    __syncthreads();

    #pragma unroll 1
    for (int e = 0; e < 4; e++) {
        float acc[2][4][4];
        #pragma unroll
        for (int mt = 0; mt < 2; mt++)
            #pragma unroll
            for (int nt = 0; nt < 4; nt++)
                #pragma unroll
                for (int r = 0; r < 4; r++) acc[mt][nt][r] = 0.f;

        #pragma unroll 1
        for (int ch = 0; ch < 16; ch++) {
            const int p = ch & 1;
            const uint32_t stage = sb + (p ? PP_ST1 : PP_ST0);

            if (ch < 15)    pp_prefA(Ab, i0, e, ch + 1, t, ra);
            else if (e < 3) pp_prefA(Ab, i0, e + 1, 0, t, ra);

            const uint32_t chb = (uint32_t)(ch * 128);
            #pragma unroll
            for (int ks = 0; ks < 4; ks++) {
                uint32_t a[2][4];
                #pragma unroll
                for (int mt = 0; mt < 2; mt++) {
                    uint32_t off = sw128((uint32_t)((a_r + mt * 16) * 128 + ks * 32 + a_kb));
                    ldsm_x4(a[mt], stage + off);
                }
                uint32_t bf[4][2];
                #pragma unroll
                for (int nt = 0; nt < 4; nt++) {
                    int d = wn * 32 + nt * 8 + b_rl;
                    uint32_t off = (uint32_t)(d * 2048)
                                 + ((chb + ks * 32 + b_kb) ^ ((uint32_t)(d & 7) << 4));
                    ldsm_x2(bf[nt], sb + PP_STT + off);
                }
                #pragma unroll
                for (int mt = 0; mt < 2; mt++)
                    #pragma unroll
                    for (int nt = 0; nt < 4; nt++)
                        mma_f16(acc[mt][nt], a[mt], bf[nt]);
            }
            if (ch < 15) pp_storeA(smem + ((p ^ 1) ? PP_ST1 : PP_ST0), t, ra);
            __syncthreads();
        }

        // ---- stage P as fp16 hi/lo into ST0/ST1 ----------------------------
        {
            const int orow = wm * 32 + (lane >> 2);
            const int ocol = wn * 32 + 2 * (lane & 3);
            #pragma unroll
            for (int mt = 0; mt < 2; mt++)
                #pragma unroll
                for (int nt = 0; nt < 4; nt++) {
                    int cc = ocol + nt * 8;
                    int r1 = orow + mt * 16, r2 = r1 + 8;
                    float c0 = acc[mt][nt][0], c1 = acc[mt][nt][1];
                    float c2 = acc[mt][nt][2], c3 = acc[mt][nt][3];
                    float h0 = __half2float(__float2half_rn(c0));
                    float h1 = __half2float(__float2half_rn(c1));
                    float h2 = __half2float(__float2half_rn(c2));
                    float h3 = __half2float(__float2half_rn(c3));
                    uint32_t o1 = sw128((uint32_t)(r1 * 128 + cc * 2));
                    uint32_t o2 = sw128((uint32_t)(r2 * 128 + cc * 2));
                    *(uint32_t*)(smem + PP_ST0 + o1) = pack_f16x2(c0, c1);
                    *(uint32_t*)(smem + PP_ST1 + o1) = pack_f16x2(c0 - h0, c1 - h1);
                    *(uint32_t*)(smem + PP_ST0 + o2) = pack_f16x2(c2, c3);
                    *(uint32_t*)(smem + PP_ST1 + o2) = pack_f16x2(c2 - h2, c3 - h3);
                }
        }
        __syncthreads();

        // ---- combine: acc2 += Ph*Wh + Pl*Wh + Ph*Wl ------------------------
        {
            const uint32_t wbase = (uint32_t)(e * 8192);
            #pragma unroll
            for (int ks = 0; ks < 4; ks++) {
                uint32_t ph[2][4], pl[2][4];
                #pragma unroll
                for (int mt = 0; mt < 2; mt++) {
                    uint32_t off = sw128((uint32_t)((a_r + mt * 16) * 128 + ks * 32 + a_kb));
                    ldsm_x4(ph[mt], sb + PP_ST0 + off);
                    ldsm_x4(pl[mt], sb + PP_ST1 + off);
                }
                uint32_t wh[4][2], wl[4][2];
                #pragma unroll
                for (int nt = 0; nt < 4; nt++) {
                    int f = wn * 32 + nt * 8 + b_rl;
                    uint32_t off = sw128((uint32_t)(f * 128 + ks * 32 + b_kb));
                    ldsm_x2(wh[nt], sb + PP_WH + wbase + off);
                    ldsm_x2(wl[nt], sb + PP_WL + wbase + off);
                }
                #pragma unroll
                for (int mt = 0; mt < 2; mt++)
                    #pragma unroll
                    for (int nt = 0; nt < 4; nt++) {
                        mma_f16(acc2[mt][nt], ph[mt], wh[nt]);
                        mma_f16(acc2[mt][nt], pl[mt], wh[nt]);
                        mma_f16(acc2[mt][nt], ph[mt], wl[nt]);
                    }
            }
        }
        __syncthreads();
        if (e < 3) { pp_storeA(smem + PP_ST0, t, ra); __syncthreads(); }
    }

    // ---- write output ------------------------------------------------------
    const int orow = wm * 32 + (lane >> 2);
    const int ocol = wn * 32 + 2 * (lane & 3);
    #pragma unroll
    for (int mt = 0; mt < 2; mt++) {
        #pragma unroll
        for (int nt = 0; nt < 4; nt++) {
            int r1 = i0 + orow + mt * 16;
            int r2 = r1 + 8;
            int cc = ocol + nt * 8;
            if (r1 < N_)
                *(float2*)(O + (size_t)r1 * D_ + cc) =
                    make_float2(acc2[mt][nt][0], acc2[mt][nt][1]);
            if (r2 < N_)
                *(float2*)(O + (size_t)r2 * D_ + cc) =
                    make_float2(acc2[mt][nt][2], acc2[mt][nt][3]);
        }
    }
}

// ============================================================================
// Kernel 3: gates + state update (unchanged)
// ============================================================================
__global__ __launch_bounds__(256) void k_gates(
    const float* __restrict__ prop_state,
    int round)
{
    const float* state = round ? g_st1 : prop_state;
    float* out_state   = round ? g_st2 : g_st1;
    const int b  = blockIdx.y;
    const int j0 = blockIdx.x * 64;

    extern __shared__ float smg[];
    float* a_sm = smg;
    float* Wr   = smg + 64 * 196;
    float* Wz   = Wr + 192 * 64;
    float* Wh   = Wz + 192 * 64;

    const int t = threadIdx.x;
    const float* ai = g_a_in  + (size_t)b * N_ * D_;
    const float* ao = g_a_out + (size_t)b * N_ * D_;
    const float* st = state   + (size_t)b * N_ * D_;

    #pragma unroll
    for (int i = 0; i < 4; i++) {
        int idx = t + i * 256;
        int j = idx >> 4, fq = (idx & 15) << 2;
        int row = j0 + j;
        float4 z4 = make_float4(0.f, 0.f, 0.f, 0.f);
        size_t g = (size_t)row * D_ + fq;
        bool v = (row < N_);
        *(float4*)&a_sm[j * 196 +       fq] = v ? *(const float4*)(ai + g) : z4;
        *(float4*)&a_sm[j * 196 +  64 + fq] = v ? *(const float4*)(ao + g) : z4;
        *(float4*)&a_sm[j * 196 + 128 + fq] = v ? *(const float4*)(st + g) : z4;
    }
    #pragma unroll
    for (int i = 0; i < 12; i++) {
        int idx4 = (t + i * 256) * 4;
        *(float4*)&Wr[idx4] = *(const float4*)(g_WrT + idx4);
        *(float4*)&Wz[idx4] = *(const float4*)(g_WzT + idx4);
        *(float4*)&Wh[idx4] = *(const float4*)(g_WhT + idx4);
    }
    __syncthreads();

    const int tx = t & 15, ty = t >> 4;
    const int r0 = ty * 4, c0 = tx * 4;

    float aR[4][4], aZ[4][4];
    #pragma unroll
    for (int i = 0; i < 4; i++)
        #pragma unroll
        for (int j = 0; j < 4; j++) { aR[i][j] = 0.f; aZ[i][j] = 0.f; }

    #pragma unroll 8
    for (int k = 0; k < 192; k++) {
        float a0 = a_sm[(r0 + 0) * 196 + k];
        float a1 = a_sm[(r0 + 1) * 196 + k];
        float a2 = a_sm[(r0 + 2) * 196 + k];
        float a3 = a_sm[(r0 + 3) * 196 + k];
        float4 wr = *(const float4*)&Wr[k * 64 + c0];
        float4 wz = *(const float4*)&Wz[k * 64 + c0];
        aR[0][0] += a0 * wr.x; aR[0][1] += a0 * wr.y; aR[0][2] += a0 * wr.z; aR[0][3] += a0 * wr.w;
        aR[1][0] += a1 * wr.x; aR[1][1] += a1 * wr.y; aR[1][2] += a1 * wr.z; aR[1][3] += a1 * wr.w;
        aR[2][0] += a2 * wr.x; aR[2][1] += a2 * wr.y; aR[2][2] += a2 * wr.z; aR[2][3] += a2 * wr.w;
        aR[3][0] += a3 * wr.x; aR[3][1] += a3 * wr.y; aR[3][2] += a3 * wr.z; aR[3][3] += a3 * wr.w;
        aZ[0][0] += a0 * wz.x; aZ[0][1] += a0 * wz.y; aZ[0][2] += a0 * wz.z; aZ[0][3] += a0 * wz.w;
        aZ[1][0] += a1 * wz.x; aZ[1][1] += a1 * wz.y; aZ[1][2] += a1 * wz.z; aZ[1][3] += a1 * wz.w;
        aZ[2][0] += a2 * wz.x; aZ[2][1] += a2 * wz.y; aZ[2][2] += a2 * wz.z; aZ[2][3] += a2 * wz.w;
        aZ[3][0] += a3 * wz.x; aZ[3][1] += a3 * wz.y; aZ[3][2] += a3 * wz.z; aZ[3][3] += a3 * wz.w;
    }

    float rg[4][4], zg[4][4], sOrig[4][4];
    #pragma unroll
    for (int i = 0; i < 4; i++)
        #pragma unroll
        for (int j = 0; j < 4; j++) {
            rg[i][j] = 1.f / (1.f + expf(-aR[i][j]));
            zg[i][j] = 1.f / (1.f + expf(-aZ[i][j]));
            sOrig[i][j] = a_sm[(r0 + i) * 196 + 128 + c0 + j];
        }
    __syncthreads();
    #pragma unroll
    for (int i = 0; i < 4; i++)
        #pragma unroll
        for (int j = 0; j < 4; j++)
            a_sm[(r0 + i) * 196 + 128 + c0 + j] = rg[i][j] * sOrig[i][j];
    __syncthreads();

    float aH[4][4];
    #pragma unroll
    for (int i = 0; i < 4; i++)
        #pragma unroll
        for (int j = 0; j < 4; j++) aH[i][j] = 0.f;

    #pragma unroll 8
    for (int k = 0; k < 192; k++) {
        float a0 = a_sm[(r0 + 0) * 196 + k];
        float a1 = a_sm[(r0 + 1) * 196 + k];
        float a2 = a_sm[(r0 + 2) * 196 + k];
        float a3 = a_sm[(r0 + 3) * 196 + k];
        float4 wh = *(const float4*)&Wh[k * 64 + c0];
        aH[0][0] += a0 * wh.x; aH[0][1] += a0 * wh.y; aH[0][2] += a0 * wh.z; aH[0][3] += a0 * wh.w;
        aH[1][0] += a1 * wh.x; aH[1][1] += a1 * wh.y; aH[1][2] += a1 * wh.z; aH[1][3] += a1 * wh.w;
        aH[2][0] += a2 * wh.x; aH[2][1] += a2 * wh.y; aH[2][2] += a2 * wh.z; aH[2][3] += a2 * wh.w;
        aH[3][0] += a3 * wh.x; aH[3][1] += a3 * wh.y; aH[3][2] += a3 * wh.z; aH[3][3] += a3 * wh.w;
    }

    float* od = out_state + (size_t)b * N_ * D_;
    #pragma unroll
    for (int i = 0; i < 4; i++) {
        int row = j0 + r0 + i;
        if (row < N_) {
            float o[4];
            #pragma unroll
            for (int j = 0; j < 4; j++) {
                float h = tanhf(aH[i][j]);
                o[j] = (1.f - zg[i][j]) * sOrig[i][j] + zg[i][j] * h;
            }
            *(float4*)(od + (size_t)row * D_ + c0) = make_float4(o[0], o[1], o[2], o[3]);
        }
    }
}

// ============================================================================
// Kernel 4: readout (unchanged)
// ============================================================================
__global__ __launch_bounds__(256) void k_readout(
    const float* __restrict__ annot,
    const float* __restrict__ Wo1,
    const float* __restrict__ Wo2,
    float* __restrict__ out)
{
    __shared__ float W1[64 * 97];
    __shared__ float W2s[64];
    __shared__ float rowbuf[4][96];
    __shared__ float partial[4][2];

    const int t = threadIdx.x;
    for (int i = t; i < 64 * 96; i += 256) {
        int f = i / 96, k = i - f * 96;
        W1[f * 97 + k] = Wo1[i];
    }
    if (t < 64) W2s[t] = Wo2[t];

    const int slot = t >> 6;
    const int lane = t & 63;
    const int row  = blockIdx.x * 4 + slot;
    const int b    = row / N_;
    const int i    = row - b * N_;

    for (int k = lane; k < 96; k += 64) {
        float v = (k < 64) ? g_st2[((size_t)b * N_ + i) * D_ + k]
                           : annot[((size_t)b * N_ + i) * AD_ + (k - 64)];
        rowbuf[slot][k] = v;
    }
    __syncthreads();

    float acc = 0.f;
    #pragma unroll 8
    for (int k = 0; k < 96; k++)
        acc += rowbuf[slot][k] * W1[lane * 97 + k];
    float v = tanhf(acc) * W2s[lane];

    #pragma unroll
    for (int off = 16; off > 0; off >>= 1)
        v += __shfl_down_sync(0xffffffffu, v, off);
    if ((t & 31) == 0) partial[slot][(t >> 5) & 1] = v;
    __syncthreads();
    if (lane == 0) out[row] = partial[slot][0] + partial[slot][1];
}

// ============================================================================
extern "C" void kernel_launch(void* const* d_in, const int* in_sizes, int n_in,
                              void* d_out, int out_size)
{
    const float* prop_state = (const float*)d_in[0];
    const float* annotation = (const float*)d_in[1];
    const float* A          = (const float*)d_in[2];
    const float* W_in       = (const float*)d_in[3];
    const float* W_out      = (const float*)d_in[4];
    const float* W_r        = (const float*)d_in[5];
    const float* W_z        = (const float*)d_in[6];
    const float* W_h        = (const float*)d_in[7];
    const float* Wo1        = (const float*)d_in[8];
    const float* Wo2        = (const float*)d_in[9];
    float* out = (float*)d_out;

    const int GATES_SMEM = (64 * 196 + 3 * 192 * 64) * (int)sizeof(float);
    cudaFuncSetAttribute(k_gates, cudaFuncAttributeMaxDynamicSharedMemorySize, GATES_SMEM);
    cudaFuncSetAttribute(k_prop, cudaFuncAttributeMaxDynamicSharedMemorySize, PP_SMEM);

    k_pret<<<128, 256>>>(W_r, W_z, W_h, W_in, W_out);
    for (int round = 0; round < 2; round++) {
        k_stT<<<dim3(16, B_), 256>>>(prop_state, round);
        k_prop<<<dim3(8, B_, 2), 256, PP_SMEM>>>(A);
        k_gates<<<dim3(16, B_), 256, GATES_SMEM>>>(prop_state, round);
    }
    k_readout<<<2000, 256>>>(annotation, Wo1, Wo2, out);
}